// round 15
// baseline (speedup 1.0000x reference)
#include <cuda_runtime.h>
#include <cuda_fp16.h>
#include <cstdint>
#include <cstddef>

// ===================== problem constants =====================
static constexpr int T_TOK = 8192;   // B*S tokens
static constexpr int D_DIM = 2048;
static constexpr int E_NUM = 8;
static constexpr int I_DIM = 4096;
static constexpr int R_MAX = 16384;  // routed rows = 2*T always
static constexpr int R_PAD = 16512;  // + one tile of slack
static constexpr int MAX_SLOTS = 144;
static constexpr int HALF_SLOTS = 72;

static constexpr size_t WS16_ELEMS  = (size_t)E_NUM * 2 * I_DIM * D_DIM;
static constexpr size_t W2S16_ELEMS = (size_t)E_NUM * D_DIM * I_DIM;

// ===================== device scratch (no allocs allowed) =====================
__device__ __align__(256) __half g_ws16 [WS16_ELEMS];
__device__ __align__(256) __half g_w2s16[W2S16_ELEMS];
__device__ __align__(256) __half g_X    [(size_t)R_PAD * D_DIM];
__device__ __align__(256) __half g_act  [(size_t)R_PAD * I_DIM];
__device__ __align__(256) float  g_out2 [(size_t)R_PAD * D_DIM];
__device__ int   g_topk_id[T_TOK * 2];
__device__ float g_topk_w [T_TOK * 2];
__device__ int   g_count [E_NUM];
__device__ int   g_cursor[E_NUM];
__device__ int   g_offset[E_NUM + 1];
__device__ int   g_row_token[R_MAX];
__device__ int   g_tok_pos[T_TOK * 2];
__device__ int   g_slot_e [MAX_SLOTS];
__device__ int   g_slot_r0[MAX_SLOTS];
__device__ int   g_slot_n [MAX_SLOTS];

// ===================== base-target PTX helpers (<= sm_90, no 'a' features) ====
__device__ __forceinline__ uint32_t smem_u32(const void* p) {
    uint32_t a;
    asm("{ .reg .u64 t; cvta.to.shared.u64 t, %1; cvt.u32.u64 %0, t; }" : "=r"(a) : "l"(p));
    return a;
}
__device__ __forceinline__ void cpa16(uint32_t saddr, const void* g) {
    asm volatile("cp.async.cg.shared.global [%0], [%1], 16;" :: "r"(saddr), "l"(g) : "memory");
}
#define CP_COMMIT() asm volatile("cp.async.commit_group;" ::: "memory")
#define CP_WAIT2()  asm volatile("cp.async.wait_group 2;" ::: "memory")

__device__ __forceinline__ void ldsm4(uint32_t& r0, uint32_t& r1, uint32_t& r2, uint32_t& r3,
                                      uint32_t addr) {
    asm volatile("ldmatrix.sync.aligned.m8n8.x4.shared.b16 {%0,%1,%2,%3}, [%4];"
                 : "=r"(r0), "=r"(r1), "=r"(r2), "=r"(r3) : "r"(addr));
}
__device__ __forceinline__ void mma16816(float* c, const uint32_t* a, const uint32_t* b) {
    asm volatile("mma.sync.aligned.m16n8k16.row.col.f32.f16.f16.f32 "
                 "{%0,%1,%2,%3}, {%4,%5,%6,%7}, {%8,%9}, {%0,%1,%2,%3};"
                 : "+f"(c[0]), "+f"(c[1]), "+f"(c[2]), "+f"(c[3])
                 : "r"(a[0]), "r"(a[1]), "r"(a[2]), "r"(a[3]), "r"(b[0]), "r"(b[1]));
}

// smem tile: rows x 64 halfs (128B/row), 16B chunks swizzled c16 ^ (r&7).
__device__ __forceinline__ uint32_t sm_off(int r, int c16) {
    return (uint32_t)(r * 128 + ((c16 ^ (r & 7)) * 16));
}

__device__ __forceinline__ unsigned h2u(__half2 v) { return *reinterpret_cast<unsigned*>(&v); }

// ===================== small kernels =====================
__global__ void reset_kernel() {
    if (threadIdx.x < E_NUM) g_count[threadIdx.x] = 0;
}

__global__ void convert_kernel(const float* __restrict__ src, __half* __restrict__ dst, int n4) {
    int i = blockIdx.x * blockDim.x + threadIdx.x;
    if (i >= n4) return;
    float4 v = reinterpret_cast<const float4*>(src)[i];
    __half2 a = __floats2half2_rn(v.x, v.y);
    __half2 b = __floats2half2_rn(v.z, v.w);
    reinterpret_cast<uint2*>(dst)[i] = make_uint2(h2u(a), h2u(b));
}

__global__ void router_kernel(const float* __restrict__ h, const float* __restrict__ rw) {
    extern __shared__ char dynsm_raw[];
    float4* srw4 = reinterpret_cast<float4*>(dynsm_raw);   // [E][512] float4
    int tid = threadIdx.x;
    const float4* rw4 = reinterpret_cast<const float4*>(rw);
    for (int i = tid; i < E_NUM * 512; i += 256) srw4[i] = rw4[i];
    __syncthreads();

    int warp = tid >> 5, lane = tid & 31;
    int t = blockIdx.x * 8 + warp;
    const float4* hv = reinterpret_cast<const float4*>(h) + (size_t)t * 512;
    float acc[E_NUM];
    #pragma unroll
    for (int e = 0; e < E_NUM; e++) acc[e] = 0.f;
    #pragma unroll 4
    for (int jj = 0; jj < 16; jj++) {
        float4 x = hv[lane + 32 * jj];
        #pragma unroll
        for (int e = 0; e < E_NUM; e++) {
            float4 w = srw4[e * 512 + lane + 32 * jj];
            acc[e] += x.x * w.x + x.y * w.y + x.z * w.z + x.w * w.w;
        }
    }
    #pragma unroll
    for (int e = 0; e < E_NUM; e++)
        #pragma unroll
        for (int o = 16; o > 0; o >>= 1) acc[e] += __shfl_xor_sync(0xFFFFFFFFu, acc[e], o);
    if (lane == 0) {
        float m = acc[0];
        #pragma unroll
        for (int e = 1; e < E_NUM; e++) m = fmaxf(m, acc[e]);
        float p[E_NUM], s = 0.f;
        #pragma unroll
        for (int e = 0; e < E_NUM; e++) { p[e] = expf(acc[e] - m); s += p[e]; }
        int i0 = 0;
        #pragma unroll
        for (int e = 1; e < E_NUM; e++) if (p[e] > p[i0]) i0 = e;
        int i1 = (i0 == 0) ? 1 : 0;
        #pragma unroll
        for (int e = 0; e < E_NUM; e++) if (e != i0 && p[e] > p[i1]) i1 = e;
        float inv = 1.f / s;
        g_topk_id[2 * t + 0] = i0;  g_topk_w[2 * t + 0] = p[i0] * inv;
        g_topk_id[2 * t + 1] = i1;  g_topk_w[2 * t + 1] = p[i1] * inv;
        atomicAdd(&g_count[i0], 1);
        atomicAdd(&g_count[i1], 1);
    }
}

__global__ void offsets_kernel() {
    if (threadIdx.x != 0 || blockIdx.x != 0) return;
    int off = 0;
    for (int e = 0; e < E_NUM; e++) { g_offset[e] = off; g_cursor[e] = off; off += g_count[e]; }
    g_offset[E_NUM] = off;
    int s = 0;
    for (int e = 0; e < E_NUM; e++) {
        for (int r0 = g_offset[e]; r0 < g_offset[e + 1]; r0 += 128) {
            g_slot_e[s] = e;  g_slot_r0[s] = r0;
            int n = g_offset[e + 1] - r0;  g_slot_n[s] = n < 128 ? n : 128;
            s++;
        }
    }
    for (; s < MAX_SLOTS; s++) g_slot_e[s] = -1;
}

__global__ void scatter_kernel() {
    int t = blockIdx.x * blockDim.x + threadIdx.x;
    if (t >= T_TOK) return;
    #pragma unroll
    for (int k = 0; k < 2; k++) {
        int e = g_topk_id[2 * t + k];
        int pos = atomicAdd(&g_cursor[e], 1);
        g_row_token[pos] = t;
        g_tok_pos[2 * t + k] = pos;
    }
}

__global__ void gather_kernel(const float* __restrict__ h) {
    int r = blockIdx.x;
    int t = g_row_token[r];
    const float4* src = reinterpret_cast<const float4*>(h) + (size_t)t * (D_DIM / 4);
    uint2* dst = reinterpret_cast<uint2*>(g_X + (size_t)r * D_DIM);
    for (int i = threadIdx.x; i < D_DIM / 4; i += 256) {
        float4 v = src[i];
        __half2 a = __floats2half2_rn(v.x, v.y);
        __half2 b = __floats2half2_rn(v.z, v.w);
        dst[i] = make_uint2(h2u(a), h2u(b));
    }
}

// ===================== GEMM kernels =====================
// BK=64. Stage: A 128x64 halfs (16KB) + B 256x64 halfs (32KB) = 48KB; 4 stages.
static constexpr int STAGE_B = 49152;
static constexpr int NSTAGE = 4;

// GEMM1: act = silu(X Wg^T) * (X Wu^T). grid (I/128, HALF_SLOTS), 256 thr.
// CTA: 128 rows x (128 gate + 128 up). Warps 2m x 4n; warp tile 64 x (32g+32u).
__global__ __launch_bounds__(256, 1) void gemm1_kernel(int slot_base) {
    int slot = slot_base + blockIdx.y;
    int e = g_slot_e[slot];
    if (e < 0) return;
    int r0 = g_slot_r0[slot];
    int nrows = g_slot_n[slot];
    int n0 = blockIdx.x * 128;

    extern __shared__ char dynsm_raw[];
    uint32_t smb = smem_u32(dynsm_raw);

    int tid = threadIdx.x;
    int lane = tid & 31, w = tid >> 5;
    int wm = w & 1, wn = w >> 1;          // 2m x 4n

    const __half* Wg = g_ws16 + (size_t)e * (2 * I_DIM) * D_DIM + (size_t)n0 * D_DIM;
    const __half* Wu = g_ws16 + (size_t)e * (2 * I_DIM) * D_DIM + (size_t)(I_DIM + n0) * D_DIM;
    const __half* X  = g_X + (size_t)r0 * D_DIM;

    int lr = tid >> 3, lc = tid & 7;      // base row, chunk

    auto load_stage = [&](int c, int s) {
        uint32_t sb = smb + s * STAGE_B;
        int k0 = c * 64;
        #pragma unroll
        for (int i = 0; i < 4; i++) {     // A rows 0..127
            int r = lr + 32 * i;
            cpa16(sb + sm_off(r, lc), X + (size_t)r * D_DIM + k0 + lc * 8);
        }
        #pragma unroll
        for (int i = 0; i < 4; i++) {     // B gate rows 0..127
            int r = lr + 32 * i;
            cpa16(sb + 16384 + sm_off(r, lc), Wg + (size_t)r * D_DIM + k0 + lc * 8);
        }
        #pragma unroll
        for (int i = 0; i < 4; i++) {     // B up rows 128..255
            int r = lr + 32 * i;
            cpa16(sb + 16384 + sm_off(128 + r, lc), Wu + (size_t)r * D_DIM + k0 + lc * 8);
        }
    };

    float cg[4][4][4] = {};
    float cu[4][4][4] = {};

    const int NC = D_DIM / 64;   // 32
    load_stage(0, 0); CP_COMMIT();
    load_stage(1, 1); CP_COMMIT();
    load_stage(2, 2); CP_COMMIT();

    for (int c = 0; c < NC; c++) {
        CP_WAIT2();
        __syncthreads();
        int cn = c + 3;
        if (cn < NC) load_stage(cn, cn % NSTAGE);
        CP_COMMIT();
        uint32_t sA = smb + (c % NSTAGE) * STAGE_B;
        uint32_t sB = sA + 16384;
        #pragma unroll
        for (int ks = 0; ks < 4; ks++) {
            int c16 = ks * 2 + (lane >> 4);
            uint32_t a[4][4];
            #pragma unroll
            for (int mi = 0; mi < 4; mi++) {
                int r = wm * 64 + mi * 16 + (lane & 15);
                ldsm4(a[mi][0], a[mi][1], a[mi][2], a[mi][3], sA + sm_off(r, c16));
            }
            uint32_t bg[4][2], bu[4][2];
            #pragma unroll
            for (int nb = 0; nb < 2; nb++) {
                uint32_t t0, t1, t2, t3;
                int rg = wn * 32 + nb * 16 + (lane & 15);
                ldsm4(t0, t1, t2, t3, sB + sm_off(rg, c16));
                bg[nb * 2][0] = t0; bg[nb * 2][1] = t2;
                bg[nb * 2 + 1][0] = t1; bg[nb * 2 + 1][1] = t3;
                int ru = 128 + wn * 32 + nb * 16 + (lane & 15);
                ldsm4(t0, t1, t2, t3, sB + sm_off(ru, c16));
                bu[nb * 2][0] = t0; bu[nb * 2][1] = t2;
                bu[nb * 2 + 1][0] = t1; bu[nb * 2 + 1][1] = t3;
            }
            #pragma unroll
            for (int mi = 0; mi < 4; mi++)
                #pragma unroll
                for (int ni = 0; ni < 4; ni++) {
                    mma16816(cg[mi][ni], a[mi], bg[ni]);
                    mma16816(cu[mi][ni], a[mi], bu[ni]);
                }
        }
    }

    // epilogue: silu(g)*u -> fp16
    #pragma unroll
    for (int mi = 0; mi < 4; mi++) {
        int row = wm * 64 + mi * 16 + (lane >> 2);
        #pragma unroll
        for (int ni = 0; ni < 4; ni++) {
            int col = n0 + wn * 32 + ni * 8 + (lane & 3) * 2;
            float g0 = cg[mi][ni][0], g1 = cg[mi][ni][1];
            float u0 = cu[mi][ni][0], u1 = cu[mi][ni][1];
            float a0 = g0 * u0 / (1.f + __expf(-g0));
            float a1 = g1 * u1 / (1.f + __expf(-g1));
            if (row < nrows)
                *reinterpret_cast<__half2*>(g_act + (size_t)(r0 + row) * I_DIM + col) =
                    __floats2half2_rn(a0, a1);
            float g2 = cg[mi][ni][2], g3 = cg[mi][ni][3];
            float u2 = cu[mi][ni][2], u3 = cu[mi][ni][3];
            float a2 = g2 * u2 / (1.f + __expf(-g2));
            float a3 = g3 * u3 / (1.f + __expf(-g3));
            if (row + 8 < nrows)
                *reinterpret_cast<__half2*>(g_act + (size_t)(r0 + row + 8) * I_DIM + col) =
                    __floats2half2_rn(a2, a3);
        }
    }
}

// GEMM2: out2 = act W2^T (fp32). grid (D/256, HALF_SLOTS), 256 thr.
// CTA: 128 rows x 256 cols, K=4096. Warps 2m x 4n; warp tile 64x64.
__global__ __launch_bounds__(256, 1) void gemm2_kernel(int slot_base) {
    int slot = slot_base + blockIdx.y;
    int e = g_slot_e[slot];
    if (e < 0) return;
    int r0 = g_slot_r0[slot];
    int nrows = g_slot_n[slot];
    int n0 = blockIdx.x * 256;

    extern __shared__ char dynsm_raw[];
    uint32_t smb = smem_u32(dynsm_raw);

    int tid = threadIdx.x;
    int lane = tid & 31, w = tid >> 5;
    int wm = w & 1, wn = w >> 1;          // 2m x 4n

    const __half* W2 = g_w2s16 + (size_t)e * D_DIM * I_DIM + (size_t)n0 * I_DIM;
    const __half* A  = g_act + (size_t)r0 * I_DIM;

    int lr = tid >> 3, lc = tid & 7;

    auto load_stage = [&](int c, int s) {
        uint32_t sb = smb + s * STAGE_B;
        int k0 = c * 64;
        #pragma unroll
        for (int i = 0; i < 4; i++) {     // A rows 0..127
            int r = lr + 32 * i;
            cpa16(sb + sm_off(r, lc), A + (size_t)r * I_DIM + k0 + lc * 8);
        }
        #pragma unroll
        for (int i = 0; i < 8; i++) {     // B rows 0..255
            int r = lr + 32 * i;
            cpa16(sb + 16384 + sm_off(r, lc), W2 + (size_t)r * I_DIM + k0 + lc * 8);
        }
    };

    float acc[4][8][4] = {};

    const int NC = I_DIM / 64;   // 64
    load_stage(0, 0); CP_COMMIT();
    load_stage(1, 1); CP_COMMIT();
    load_stage(2, 2); CP_COMMIT();

    for (int c = 0; c < NC; c++) {
        CP_WAIT2();
        __syncthreads();
        int cn = c + 3;
        if (cn < NC) load_stage(cn, cn % NSTAGE);
        CP_COMMIT();
        uint32_t sA = smb + (c % NSTAGE) * STAGE_B;
        uint32_t sB = sA + 16384;
        #pragma unroll
        for (int ks = 0; ks < 4; ks++) {
            int c16 = ks * 2 + (lane >> 4);
            uint32_t a[4][4];
            #pragma unroll
            for (int mi = 0; mi < 4; mi++) {
                int r = wm * 64 + mi * 16 + (lane & 15);
                ldsm4(a[mi][0], a[mi][1], a[mi][2], a[mi][3], sA + sm_off(r, c16));
            }
            uint32_t b[8][2];
            #pragma unroll
            for (int nb = 0; nb < 4; nb++) {
                uint32_t t0, t1, t2, t3;
                int rb = wn * 64 + nb * 16 + (lane & 15);
                ldsm4(t0, t1, t2, t3, sB + sm_off(rb, c16));
                b[nb * 2][0] = t0; b[nb * 2][1] = t2;
                b[nb * 2 + 1][0] = t1; b[nb * 2 + 1][1] = t3;
            }
            #pragma unroll
            for (int mi = 0; mi < 4; mi++)
                #pragma unroll
                for (int ni = 0; ni < 8; ni++)
                    mma16816(acc[mi][ni], a[mi], b[ni]);
        }
    }

    #pragma unroll
    for (int mi = 0; mi < 4; mi++) {
        int row = wm * 64 + mi * 16 + (lane >> 2);
        #pragma unroll
        for (int ni = 0; ni < 8; ni++) {
            int col = n0 + wn * 64 + ni * 8 + (lane & 3) * 2;
            if (row < nrows)
                *reinterpret_cast<float2*>(g_out2 + (size_t)(r0 + row) * D_DIM + col) =
                    make_float2(acc[mi][ni][0], acc[mi][ni][1]);
            if (row + 8 < nrows)
                *reinterpret_cast<float2*>(g_out2 + (size_t)(r0 + row + 8) * D_DIM + col) =
                    make_float2(acc[mi][ni][2], acc[mi][ni][3]);
        }
    }
}

__global__ void combine_kernel(float* __restrict__ out) {
    int t = blockIdx.x;
    float w0 = g_topk_w[2 * t], w1 = g_topk_w[2 * t + 1];
    int p0 = g_tok_pos[2 * t], p1 = g_tok_pos[2 * t + 1];
    const float4* a = reinterpret_cast<const float4*>(g_out2 + (size_t)p0 * D_DIM);
    const float4* b = reinterpret_cast<const float4*>(g_out2 + (size_t)p1 * D_DIM);
    float4* o = reinterpret_cast<float4*>(out + (size_t)t * D_DIM);
    for (int i = threadIdx.x; i < D_DIM / 4; i += 256) {
        float4 va = a[i], vb = b[i];
        o[i] = make_float4(w0 * va.x + w1 * vb.x, w0 * va.y + w1 * vb.y,
                           w0 * va.z + w1 * vb.z, w0 * va.w + w1 * vb.w);
    }
}

// ===================== launcher =====================
extern "C" void kernel_launch(void* const* d_in, const int* in_sizes, int n_in,
                              void* d_out, int out_size) {
    const float* h   = (const float*)d_in[0];   // [B,S,D]
    const float* rw  = (const float*)d_in[1];   // [E,D]
    const float* ws  = (const float*)d_in[2];   // [E,2I,D]
    const float* w2s = (const float*)d_in[3];   // [E,D,I]
    float* out = (float*)d_out;

    static const size_t SM_ROUTER = (size_t)E_NUM * D_DIM * sizeof(float);  // 64 KB
    static const size_t SM_GEMM = (size_t)NSTAGE * STAGE_B;                 // 192 KB
    cudaFuncSetAttribute(router_kernel, cudaFuncAttributeMaxDynamicSharedMemorySize, (int)SM_ROUTER);
    cudaFuncSetAttribute(gemm1_kernel,  cudaFuncAttributeMaxDynamicSharedMemorySize, (int)SM_GEMM);
    cudaFuncSetAttribute(gemm2_kernel,  cudaFuncAttributeMaxDynamicSharedMemorySize, (int)SM_GEMM);

    __half* ws16_p;  cudaGetSymbolAddress((void**)&ws16_p,  g_ws16);
    __half* w2s16_p; cudaGetSymbolAddress((void**)&w2s16_p, g_w2s16);

    // Lazily created host-side resources (identical captured work every call).
    static cudaStream_t s2 = nullptr;
    static cudaEvent_t evFork = nullptr, evWs = nullptr, evW2s = nullptr;
    static cudaEvent_t evG1a = nullptr, evG1b = nullptr, evG2 = nullptr;
    if (s2 == nullptr) {
        cudaStreamCreate(&s2);
        cudaEventCreateWithFlags(&evFork, cudaEventDisableTiming);
        cudaEventCreateWithFlags(&evWs,   cudaEventDisableTiming);
        cudaEventCreateWithFlags(&evW2s,  cudaEventDisableTiming);
        cudaEventCreateWithFlags(&evG1a,  cudaEventDisableTiming);
        cudaEventCreateWithFlags(&evG1b,  cudaEventDisableTiming);
        cudaEventCreateWithFlags(&evG2,   cudaEventDisableTiming);
    }

    // Fork: weight conversion on s2, routing chain on the default stream.
    cudaEventRecord(evFork, 0);
    cudaStreamWaitEvent(s2, evFork, 0);

    {
        int n4 = (int)(WS16_ELEMS / 4);
        convert_kernel<<<n4 / 256, 256, 0, s2>>>(ws, ws16_p, n4);
        cudaEventRecord(evWs, s2);
        int m4 = (int)(W2S16_ELEMS / 4);
        convert_kernel<<<m4 / 256, 256, 0, s2>>>(w2s, w2s16_p, m4);
    }

    // Routing chain (independent of weight conversion).
    reset_kernel<<<1, 32>>>();
    router_kernel<<<T_TOK / 8, 256, SM_ROUTER>>>(h, rw);
    offsets_kernel<<<1, 1>>>();
    scatter_kernel<<<T_TOK / 256, 256>>>();
    gather_kernel<<<R_MAX, 256>>>(h);

    // GEMM1 in two slot-halves on stream 0 (needs ws16 + gather).
    cudaStreamWaitEvent(0, evWs, 0);
    gemm1_kernel<<<dim3(I_DIM / 128, HALF_SLOTS), 256, SM_GEMM>>>(0);
    cudaEventRecord(evG1a, 0);
    gemm1_kernel<<<dim3(I_DIM / 128, HALF_SLOTS), 256, SM_GEMM>>>(HALF_SLOTS);
    cudaEventRecord(evG1b, 0);

    // GEMM2 halves on s2: g2a overlaps g1b (w2s16 already converted on s2, in-order).
    cudaStreamWaitEvent(s2, evG1a, 0);
    gemm2_kernel<<<dim3(D_DIM / 256, HALF_SLOTS), 256, SM_GEMM, s2>>>(0);
    cudaStreamWaitEvent(s2, evG1b, 0);
    gemm2_kernel<<<dim3(D_DIM / 256, HALF_SLOTS), 256, SM_GEMM, s2>>>(HALF_SLOTS);
    cudaEventRecord(evG2, s2);

    // Weighted combine on stream 0 after both GEMM2 halves.
    cudaStreamWaitEvent(0, evG2, 0);
    combine_kernel<<<T_TOK, 256>>>(out);
}

// round 17
// speedup vs baseline: 1.0569x; 1.0569x over previous
#include <cuda_runtime.h>
#include <cuda_fp16.h>
#include <cstdint>
#include <cstddef>

// ===================== problem constants =====================
static constexpr int T_TOK = 8192;   // B*S tokens
static constexpr int D_DIM = 2048;
static constexpr int E_NUM = 8;
static constexpr int I_DIM = 4096;
static constexpr int R_MAX = 16384;  // routed rows = 2*T always
static constexpr int R_PAD = 16512;  // + one tile of slack
static constexpr int MAX_SLOTS = 144;

static constexpr size_t WS16_ELEMS  = (size_t)E_NUM * 2 * I_DIM * D_DIM;
static constexpr size_t W2S16_ELEMS = (size_t)E_NUM * D_DIM * I_DIM;

// ===================== device scratch (no allocs allowed) =====================
__device__ __align__(256) __half g_ws16 [WS16_ELEMS];
__device__ __align__(256) __half g_w2s16[W2S16_ELEMS];
__device__ __align__(256) __half g_X    [(size_t)R_PAD * D_DIM];
__device__ __align__(256) __half g_act  [(size_t)R_PAD * I_DIM];
__device__ __align__(256) float  g_out2 [(size_t)R_PAD * D_DIM];
__device__ int   g_topk_id[T_TOK * 2];
__device__ float g_topk_w [T_TOK * 2];
__device__ int   g_count [E_NUM];
__device__ int   g_cursor[E_NUM];
__device__ int   g_offset[E_NUM + 1];
__device__ int   g_row_token[R_MAX];
__device__ int   g_tok_pos[T_TOK * 2];
__device__ int   g_slot_e [MAX_SLOTS];
__device__ int   g_slot_r0[MAX_SLOTS];
__device__ int   g_slot_n [MAX_SLOTS];

// ===================== base-target PTX helpers (<= sm_90, no 'a' features) ====
__device__ __forceinline__ uint32_t smem_u32(const void* p) {
    uint32_t a;
    asm("{ .reg .u64 t; cvta.to.shared.u64 t, %1; cvt.u32.u64 %0, t; }" : "=r"(a) : "l"(p));
    return a;
}
__device__ __forceinline__ void cpa16(uint32_t saddr, const void* g) {
    asm volatile("cp.async.cg.shared.global [%0], [%1], 16;" :: "r"(saddr), "l"(g) : "memory");
}
#define CP_COMMIT() asm volatile("cp.async.commit_group;" ::: "memory")
#define CP_WAIT2()  asm volatile("cp.async.wait_group 2;" ::: "memory")

__device__ __forceinline__ void ldsm4(uint32_t& r0, uint32_t& r1, uint32_t& r2, uint32_t& r3,
                                      uint32_t addr) {
    asm volatile("ldmatrix.sync.aligned.m8n8.x4.shared.b16 {%0,%1,%2,%3}, [%4];"
                 : "=r"(r0), "=r"(r1), "=r"(r2), "=r"(r3) : "r"(addr));
}
__device__ __forceinline__ void mma16816(float* c, const uint32_t* a, const uint32_t* b) {
    asm volatile("mma.sync.aligned.m16n8k16.row.col.f32.f16.f16.f32 "
                 "{%0,%1,%2,%3}, {%4,%5,%6,%7}, {%8,%9}, {%0,%1,%2,%3};"
                 : "+f"(c[0]), "+f"(c[1]), "+f"(c[2]), "+f"(c[3])
                 : "r"(a[0]), "r"(a[1]), "r"(a[2]), "r"(a[3]), "r"(b[0]), "r"(b[1]));
}

// smem tile: rows x 64 halfs (128B/row), 16B chunks swizzled c16 ^ (r&7).
__device__ __forceinline__ uint32_t sm_off(int r, int c16) {
    return (uint32_t)(r * 128 + ((c16 ^ (r & 7)) * 16));
}

__device__ __forceinline__ unsigned h2u(__half2 v) { return *reinterpret_cast<unsigned*>(&v); }

// ===================== small kernels =====================
__global__ void reset_kernel() {
    if (threadIdx.x < E_NUM) g_count[threadIdx.x] = 0;
}

__global__ void convert_kernel(const float* __restrict__ src, __half* __restrict__ dst, int n4) {
    int i = blockIdx.x * blockDim.x + threadIdx.x;
    if (i >= n4) return;
    float4 v = reinterpret_cast<const float4*>(src)[i];
    __half2 a = __floats2half2_rn(v.x, v.y);
    __half2 b = __floats2half2_rn(v.z, v.w);
    reinterpret_cast<uint2*>(dst)[i] = make_uint2(h2u(a), h2u(b));
}

__global__ void router_kernel(const float* __restrict__ h, const float* __restrict__ rw) {
    extern __shared__ char dynsm_raw[];
    float4* srw4 = reinterpret_cast<float4*>(dynsm_raw);   // [E][512] float4
    int tid = threadIdx.x;
    const float4* rw4 = reinterpret_cast<const float4*>(rw);
    for (int i = tid; i < E_NUM * 512; i += 256) srw4[i] = rw4[i];
    __syncthreads();

    int warp = tid >> 5, lane = tid & 31;
    int t = blockIdx.x * 8 + warp;
    const float4* hv = reinterpret_cast<const float4*>(h) + (size_t)t * 512;
    float acc[E_NUM];
    #pragma unroll
    for (int e = 0; e < E_NUM; e++) acc[e] = 0.f;
    #pragma unroll 4
    for (int jj = 0; jj < 16; jj++) {
        float4 x = hv[lane + 32 * jj];
        #pragma unroll
        for (int e = 0; e < E_NUM; e++) {
            float4 w = srw4[e * 512 + lane + 32 * jj];
            acc[e] += x.x * w.x + x.y * w.y + x.z * w.z + x.w * w.w;
        }
    }
    #pragma unroll
    for (int e = 0; e < E_NUM; e++)
        #pragma unroll
        for (int o = 16; o > 0; o >>= 1) acc[e] += __shfl_xor_sync(0xFFFFFFFFu, acc[e], o);
    if (lane == 0) {
        float m = acc[0];
        #pragma unroll
        for (int e = 1; e < E_NUM; e++) m = fmaxf(m, acc[e]);
        float p[E_NUM], s = 0.f;
        #pragma unroll
        for (int e = 0; e < E_NUM; e++) { p[e] = expf(acc[e] - m); s += p[e]; }
        int i0 = 0;
        #pragma unroll
        for (int e = 1; e < E_NUM; e++) if (p[e] > p[i0]) i0 = e;
        int i1 = (i0 == 0) ? 1 : 0;
        #pragma unroll
        for (int e = 0; e < E_NUM; e++) if (e != i0 && p[e] > p[i1]) i1 = e;
        float inv = 1.f / s;
        g_topk_id[2 * t + 0] = i0;  g_topk_w[2 * t + 0] = p[i0] * inv;
        g_topk_id[2 * t + 1] = i1;  g_topk_w[2 * t + 1] = p[i1] * inv;
        atomicAdd(&g_count[i0], 1);
        atomicAdd(&g_count[i1], 1);
    }
}

__global__ void offsets_kernel() {
    if (threadIdx.x != 0 || blockIdx.x != 0) return;
    int off = 0;
    for (int e = 0; e < E_NUM; e++) { g_offset[e] = off; g_cursor[e] = off; off += g_count[e]; }
    g_offset[E_NUM] = off;
    int s = 0;
    for (int e = 0; e < E_NUM; e++) {
        for (int r0 = g_offset[e]; r0 < g_offset[e + 1]; r0 += 128) {
            g_slot_e[s] = e;  g_slot_r0[s] = r0;
            int n = g_offset[e + 1] - r0;  g_slot_n[s] = n < 128 ? n : 128;
            s++;
        }
    }
    for (; s < MAX_SLOTS; s++) g_slot_e[s] = -1;
}

__global__ void scatter_kernel() {
    int t = blockIdx.x * blockDim.x + threadIdx.x;
    if (t >= T_TOK) return;
    #pragma unroll
    for (int k = 0; k < 2; k++) {
        int e = g_topk_id[2 * t + k];
        int pos = atomicAdd(&g_cursor[e], 1);
        g_row_token[pos] = t;
        g_tok_pos[2 * t + k] = pos;
    }
}

__global__ void gather_kernel(const float* __restrict__ h) {
    int r = blockIdx.x;
    int t = g_row_token[r];
    const float4* src = reinterpret_cast<const float4*>(h) + (size_t)t * (D_DIM / 4);
    uint2* dst = reinterpret_cast<uint2*>(g_X + (size_t)r * D_DIM);
    for (int i = threadIdx.x; i < D_DIM / 4; i += 256) {
        float4 v = src[i];
        __half2 a = __floats2half2_rn(v.x, v.y);
        __half2 b = __floats2half2_rn(v.z, v.w);
        dst[i] = make_uint2(h2u(a), h2u(b));
    }
}

// ===================== GEMM kernels =====================
// BK=64. Stage: A 128x64 halfs (16KB) + B 256x64 halfs (32KB) = 48KB; 4 stages.
static constexpr int STAGE_B = 49152;
static constexpr int NSTAGE = 4;

// GEMM1: act = silu(X Wg^T) * (X Wu^T). grid (I/128, MAX_SLOTS), 256 thr.
// CTA: 128 rows x (128 gate + 128 up). Warps 2m x 4n; warp tile 64 x (32g+32u).
__global__ __launch_bounds__(256, 1) void gemm1_kernel() {
    int slot = blockIdx.y;
    int e = g_slot_e[slot];
    if (e < 0) return;
    int r0 = g_slot_r0[slot];
    int nrows = g_slot_n[slot];
    int n0 = blockIdx.x * 128;

    extern __shared__ char dynsm_raw[];
    uint32_t smb = smem_u32(dynsm_raw);

    int tid = threadIdx.x;
    int lane = tid & 31, w = tid >> 5;
    int wm = w & 1, wn = w >> 1;          // 2m x 4n

    const __half* Wg = g_ws16 + (size_t)e * (2 * I_DIM) * D_DIM + (size_t)n0 * D_DIM;
    const __half* Wu = g_ws16 + (size_t)e * (2 * I_DIM) * D_DIM + (size_t)(I_DIM + n0) * D_DIM;
    const __half* X  = g_X + (size_t)r0 * D_DIM;

    int lr = tid >> 3, lc = tid & 7;      // base row, chunk

    auto load_stage = [&](int c, int s) {
        uint32_t sb = smb + s * STAGE_B;
        int k0 = c * 64;
        #pragma unroll
        for (int i = 0; i < 4; i++) {     // A rows 0..127
            int r = lr + 32 * i;
            cpa16(sb + sm_off(r, lc), X + (size_t)r * D_DIM + k0 + lc * 8);
        }
        #pragma unroll
        for (int i = 0; i < 4; i++) {     // B gate rows 0..127
            int r = lr + 32 * i;
            cpa16(sb + 16384 + sm_off(r, lc), Wg + (size_t)r * D_DIM + k0 + lc * 8);
        }
        #pragma unroll
        for (int i = 0; i < 4; i++) {     // B up rows 128..255
            int r = lr + 32 * i;
            cpa16(sb + 16384 + sm_off(128 + r, lc), Wu + (size_t)r * D_DIM + k0 + lc * 8);
        }
    };

    float cg[4][4][4] = {};
    float cu[4][4][4] = {};

    const int NC = D_DIM / 64;   // 32
    load_stage(0, 0); CP_COMMIT();
    load_stage(1, 1); CP_COMMIT();
    load_stage(2, 2); CP_COMMIT();

    for (int c = 0; c < NC; c++) {
        CP_WAIT2();
        __syncthreads();
        int cn = c + 3;
        if (cn < NC) load_stage(cn, cn % NSTAGE);
        CP_COMMIT();
        uint32_t sA = smb + (c % NSTAGE) * STAGE_B;
        uint32_t sB = sA + 16384;
        #pragma unroll
        for (int ks = 0; ks < 4; ks++) {
            int c16 = ks * 2 + (lane >> 4);
            uint32_t a[4][4];
            #pragma unroll
            for (int mi = 0; mi < 4; mi++) {
                int r = wm * 64 + mi * 16 + (lane & 15);
                ldsm4(a[mi][0], a[mi][1], a[mi][2], a[mi][3], sA + sm_off(r, c16));
            }
            uint32_t bg[4][2], bu[4][2];
            #pragma unroll
            for (int nb = 0; nb < 2; nb++) {
                uint32_t t0, t1, t2, t3;
                int rg = wn * 32 + nb * 16 + (lane & 15);
                ldsm4(t0, t1, t2, t3, sB + sm_off(rg, c16));
                bg[nb * 2][0] = t0; bg[nb * 2][1] = t2;
                bg[nb * 2 + 1][0] = t1; bg[nb * 2 + 1][1] = t3;
                int ru = 128 + wn * 32 + nb * 16 + (lane & 15);
                ldsm4(t0, t1, t2, t3, sB + sm_off(ru, c16));
                bu[nb * 2][0] = t0; bu[nb * 2][1] = t2;
                bu[nb * 2 + 1][0] = t1; bu[nb * 2 + 1][1] = t3;
            }
            #pragma unroll
            for (int mi = 0; mi < 4; mi++)
                #pragma unroll
                for (int ni = 0; ni < 4; ni++) {
                    mma16816(cg[mi][ni], a[mi], bg[ni]);
                    mma16816(cu[mi][ni], a[mi], bu[ni]);
                }
        }
    }

    // epilogue: silu(g)*u -> fp16
    #pragma unroll
    for (int mi = 0; mi < 4; mi++) {
        int row = wm * 64 + mi * 16 + (lane >> 2);
        #pragma unroll
        for (int ni = 0; ni < 4; ni++) {
            int col = n0 + wn * 32 + ni * 8 + (lane & 3) * 2;
            float g0 = cg[mi][ni][0], g1 = cg[mi][ni][1];
            float u0 = cu[mi][ni][0], u1 = cu[mi][ni][1];
            float a0 = g0 * u0 / (1.f + __expf(-g0));
            float a1 = g1 * u1 / (1.f + __expf(-g1));
            if (row < nrows)
                *reinterpret_cast<__half2*>(g_act + (size_t)(r0 + row) * I_DIM + col) =
                    __floats2half2_rn(a0, a1);
            float g2 = cg[mi][ni][2], g3 = cg[mi][ni][3];
            float u2 = cu[mi][ni][2], u3 = cu[mi][ni][3];
            float a2 = g2 * u2 / (1.f + __expf(-g2));
            float a3 = g3 * u3 / (1.f + __expf(-g3));
            if (row + 8 < nrows)
                *reinterpret_cast<__half2*>(g_act + (size_t)(r0 + row + 8) * I_DIM + col) =
                    __floats2half2_rn(a2, a3);
        }
    }
}

// GEMM2: out2 = act W2^T (fp32). grid (D/256, MAX_SLOTS), 256 thr.
// CTA: 128 rows x 256 cols, K=4096. Warps 2m x 4n; warp tile 64x64.
__global__ __launch_bounds__(256, 1) void gemm2_kernel() {
    int slot = blockIdx.y;
    int e = g_slot_e[slot];
    if (e < 0) return;
    int r0 = g_slot_r0[slot];
    int nrows = g_slot_n[slot];
    int n0 = blockIdx.x * 256;

    extern __shared__ char dynsm_raw[];
    uint32_t smb = smem_u32(dynsm_raw);

    int tid = threadIdx.x;
    int lane = tid & 31, w = tid >> 5;
    int wm = w & 1, wn = w >> 1;          // 2m x 4n

    const __half* W2 = g_w2s16 + (size_t)e * D_DIM * I_DIM + (size_t)n0 * I_DIM;
    const __half* A  = g_act + (size_t)r0 * I_DIM;

    int lr = tid >> 3, lc = tid & 7;

    auto load_stage = [&](int c, int s) {
        uint32_t sb = smb + s * STAGE_B;
        int k0 = c * 64;
        #pragma unroll
        for (int i = 0; i < 4; i++) {     // A rows 0..127
            int r = lr + 32 * i;
            cpa16(sb + sm_off(r, lc), A + (size_t)r * I_DIM + k0 + lc * 8);
        }
        #pragma unroll
        for (int i = 0; i < 8; i++) {     // B rows 0..255
            int r = lr + 32 * i;
            cpa16(sb + 16384 + sm_off(r, lc), W2 + (size_t)r * I_DIM + k0 + lc * 8);
        }
    };

    float acc[4][8][4] = {};

    const int NC = I_DIM / 64;   // 64
    load_stage(0, 0); CP_COMMIT();
    load_stage(1, 1); CP_COMMIT();
    load_stage(2, 2); CP_COMMIT();

    for (int c = 0; c < NC; c++) {
        CP_WAIT2();
        __syncthreads();
        int cn = c + 3;
        if (cn < NC) load_stage(cn, cn % NSTAGE);
        CP_COMMIT();
        uint32_t sA = smb + (c % NSTAGE) * STAGE_B;
        uint32_t sB = sA + 16384;
        #pragma unroll
        for (int ks = 0; ks < 4; ks++) {
            int c16 = ks * 2 + (lane >> 4);
            uint32_t a[4][4];
            #pragma unroll
            for (int mi = 0; mi < 4; mi++) {
                int r = wm * 64 + mi * 16 + (lane & 15);
                ldsm4(a[mi][0], a[mi][1], a[mi][2], a[mi][3], sA + sm_off(r, c16));
            }
            uint32_t b[8][2];
            #pragma unroll
            for (int nb = 0; nb < 4; nb++) {
                uint32_t t0, t1, t2, t3;
                int rb = wn * 64 + nb * 16 + (lane & 15);
                ldsm4(t0, t1, t2, t3, sB + sm_off(rb, c16));
                b[nb * 2][0] = t0; b[nb * 2][1] = t2;
                b[nb * 2 + 1][0] = t1; b[nb * 2 + 1][1] = t3;
            }
            #pragma unroll
            for (int mi = 0; mi < 4; mi++)
                #pragma unroll
                for (int ni = 0; ni < 8; ni++)
                    mma16816(acc[mi][ni], a[mi], b[ni]);
        }
    }

    #pragma unroll
    for (int mi = 0; mi < 4; mi++) {
        int row = wm * 64 + mi * 16 + (lane >> 2);
        #pragma unroll
        for (int ni = 0; ni < 8; ni++) {
            int col = n0 + wn * 64 + ni * 8 + (lane & 3) * 2;
            if (row < nrows)
                *reinterpret_cast<float2*>(g_out2 + (size_t)(r0 + row) * D_DIM + col) =
                    make_float2(acc[mi][ni][0], acc[mi][ni][1]);
            if (row + 8 < nrows)
                *reinterpret_cast<float2*>(g_out2 + (size_t)(r0 + row + 8) * D_DIM + col) =
                    make_float2(acc[mi][ni][2], acc[mi][ni][3]);
        }
    }
}

__global__ void combine_kernel(float* __restrict__ out) {
    int t = blockIdx.x;
    float w0 = g_topk_w[2 * t], w1 = g_topk_w[2 * t + 1];
    int p0 = g_tok_pos[2 * t], p1 = g_tok_pos[2 * t + 1];
    const float4* a = reinterpret_cast<const float4*>(g_out2 + (size_t)p0 * D_DIM);
    const float4* b = reinterpret_cast<const float4*>(g_out2 + (size_t)p1 * D_DIM);
    float4* o = reinterpret_cast<float4*>(out + (size_t)t * D_DIM);
    for (int i = threadIdx.x; i < D_DIM / 4; i += 256) {
        float4 va = a[i], vb = b[i];
        o[i] = make_float4(w0 * va.x + w1 * vb.x, w0 * va.y + w1 * vb.y,
                           w0 * va.z + w1 * vb.z, w0 * va.w + w1 * vb.w);
    }
}

// ===================== launcher =====================
extern "C" void kernel_launch(void* const* d_in, const int* in_sizes, int n_in,
                              void* d_out, int out_size) {
    const float* h   = (const float*)d_in[0];   // [B,S,D]
    const float* rw  = (const float*)d_in[1];   // [E,D]
    const float* ws  = (const float*)d_in[2];   // [E,2I,D]
    const float* w2s = (const float*)d_in[3];   // [E,D,I]
    float* out = (float*)d_out;

    static const size_t SM_ROUTER = (size_t)E_NUM * D_DIM * sizeof(float);  // 64 KB
    static const size_t SM_GEMM = (size_t)NSTAGE * STAGE_B;                 // 192 KB
    cudaFuncSetAttribute(router_kernel, cudaFuncAttributeMaxDynamicSharedMemorySize, (int)SM_ROUTER);
    cudaFuncSetAttribute(gemm1_kernel,  cudaFuncAttributeMaxDynamicSharedMemorySize, (int)SM_GEMM);
    cudaFuncSetAttribute(gemm2_kernel,  cudaFuncAttributeMaxDynamicSharedMemorySize, (int)SM_GEMM);

    __half* ws16_p;  cudaGetSymbolAddress((void**)&ws16_p,  g_ws16);
    __half* w2s16_p; cudaGetSymbolAddress((void**)&w2s16_p, g_w2s16);

    // Lazily created host-side resources (identical captured work every call).
    static cudaStream_t s2 = nullptr;
    static cudaEvent_t evFork = nullptr, evWs = nullptr, evW2s = nullptr;
    if (s2 == nullptr) {
        cudaStreamCreate(&s2);
        cudaEventCreateWithFlags(&evFork, cudaEventDisableTiming);
        cudaEventCreateWithFlags(&evWs,   cudaEventDisableTiming);
        cudaEventCreateWithFlags(&evW2s,  cudaEventDisableTiming);
    }

    // Fork: weight conversion on s2, routing chain on the default stream.
    cudaEventRecord(evFork, 0);
    cudaStreamWaitEvent(s2, evFork, 0);

    {
        int n4 = (int)(WS16_ELEMS / 4);
        convert_kernel<<<n4 / 256, 256, 0, s2>>>(ws, ws16_p, n4);
        cudaEventRecord(evWs, s2);
        int m4 = (int)(W2S16_ELEMS / 4);
        convert_kernel<<<m4 / 256, 256, 0, s2>>>(w2s, w2s16_p, m4);
        cudaEventRecord(evW2s, s2);
    }

    // Routing chain (independent of weight conversion).
    reset_kernel<<<1, 32>>>();
    router_kernel<<<T_TOK / 8, 256, SM_ROUTER>>>(h, rw);
    offsets_kernel<<<1, 1>>>();
    scatter_kernel<<<T_TOK / 256, 256>>>();
    gather_kernel<<<R_MAX, 256>>>(h);

    // GEMM1 needs ws16 + gather; w2s conversion overlaps GEMM1 on s2.
    cudaStreamWaitEvent(0, evWs, 0);
    gemm1_kernel<<<dim3(I_DIM / 128, MAX_SLOTS), 256, SM_GEMM>>>();

    // GEMM2 needs w2s16 + act.
    cudaStreamWaitEvent(0, evW2s, 0);
    gemm2_kernel<<<dim3(D_DIM / 256, MAX_SLOTS), 256, SM_GEMM>>>();

    // 4) weighted combine
    combine_kernel<<<T_TOK, 256>>>(out);
}